// round 1
// baseline (speedup 1.0000x reference)
#include <cuda_runtime.h>
#include <math.h>

#define EPSF 1e-8f

// ---------------- scratch (static device globals; no allocation) -------------
static __device__ float g_Fs[10000 * 128];   // Dv^{-1/2} F, 5.12 MB (lives in L2)
static __device__ float g_deinv[5120];       // 1/(diag(De)+eps), zero-padded
static __device__ float g_blocksum[1024];    // per-block partial of S

// ---------------- packed f32x2 helpers (Blackwell FFMA2 path) ----------------
__device__ __forceinline__ unsigned long long pack2(float lo, float hi) {
    unsigned long long r;
    asm("mov.b64 %0, {%1, %2};" : "=l"(r) : "f"(lo), "f"(hi));
    return r;
}
__device__ __forceinline__ void unpack2(unsigned long long v, float& lo, float& hi) {
    asm("mov.b64 {%0, %1}, %2;" : "=f"(lo), "=f"(hi) : "l"(v));
}
__device__ __forceinline__ unsigned long long ffma2(unsigned long long a,
                                                    unsigned long long b,
                                                    unsigned long long c) {
    unsigned long long d;
    asm("fma.rn.f32x2 %0, %1, %2, %3;" : "=l"(d) : "l"(a), "l"(b), "l"(c));
    return d;
}

// ---------------- prep: Fs = F * rsqrt(diag(Dv)+eps); de_inv -----------------
__global__ void prep_kernel(const float* __restrict__ F,
                            const float* __restrict__ Dv,
                            const float* __restrict__ De,
                            int N, int E, int deinv_pad) {
    int i = blockIdx.x * blockDim.x + threadIdx.x;
    int total = N * 128;
    if (i < total) {
        int n = i >> 7;
        float dv = Dv[(size_t)n * N + n];
        g_Fs[i] = F[i] * rsqrtf(dv + EPSF);
    }
    if (i < deinv_pad) {
        float v = 0.0f;
        if (i < E) v = 1.0f / (De[(size_t)i * E + i] + EPSF);
        g_deinv[i] = v;
    }
}

// ---------------- GEMM + weighted square-reduce ------------------------------
// Tile: BE=32 (E) x BD=64 (d). Each block runs the FULL N loop for its tile,
// then locally computes sum_e de_inv[e] * sum_d M[e,d]^2 over the tile.
#define BE 32
#define BD 64
#define BN 32

__global__ void __launch_bounds__(128, 2)
gemm_kernel(const float* __restrict__ H, int N, int E, int etiles) {
    __shared__ __align__(16) float sF[BN][BD];   // 8 KB
    __shared__ __align__(16) float sH[BN][BE];   // 4 KB
    __shared__ float red[128];

    const int tile = blockIdx.x;
    const int et   = tile % etiles;
    const int dh   = tile / etiles;      // 0 or 1
    const int e0   = et * BE;
    const int d0   = dh * BD;

    const int t  = threadIdx.x;
    const int td = t & 15;               // 16 d-groups of 4
    const int te = t >> 4;               // 8 e-groups of 4

    unsigned long long a00 = 0, a01 = 0, a10 = 0, a11 = 0;
    unsigned long long a20 = 0, a21 = 0, a30 = 0, a31 = 0;

    for (int nb = 0; nb < N; nb += BN) {
        __syncthreads();
        // load Fs tile [BN x BD] (row = n, contiguous d)
        {
            int c = (t & 15) * 4;
            #pragma unroll
            for (int rr = (t >> 4); rr < BN; rr += 8) {
                int n = nb + rr;
                float4 v = make_float4(0.f, 0.f, 0.f, 0.f);
                if (n < N) v = *(const float4*)&g_Fs[(size_t)n * 128 + d0 + c];
                *(float4*)&sF[rr][c] = v;
            }
        }
        // load H tile [BN x BE] (row = n, contiguous e)
        {
            int c = (t & 7) * 4;
            #pragma unroll
            for (int rr = (t >> 3); rr < BN; rr += 16) {
                int n = nb + rr;
                int e = e0 + c;
                float4 v = make_float4(0.f, 0.f, 0.f, 0.f);
                if (n < N) {
                    if (e + 3 < E) {
                        v = *(const float4*)&H[(size_t)n * E + e];
                    } else {
                        const float* row = H + (size_t)n * E;
                        if (e + 0 < E) v.x = row[e + 0];
                        if (e + 1 < E) v.y = row[e + 1];
                        if (e + 2 < E) v.z = row[e + 2];
                        if (e + 3 < E) v.w = row[e + 3];
                    }
                }
                *(float4*)&sH[rr][c] = v;
            }
        }
        __syncthreads();

        #pragma unroll 8
        for (int kk = 0; kk < BN; ++kk) {
            ulonglong2 f = *(const ulonglong2*)&sF[kk][td * 4];
            float4 hv = *(const float4*)&sH[kk][te * 4];
            unsigned long long h0 = pack2(hv.x, hv.x);
            unsigned long long h1 = pack2(hv.y, hv.y);
            unsigned long long h2 = pack2(hv.z, hv.z);
            unsigned long long h3 = pack2(hv.w, hv.w);
            a00 = ffma2(h0, f.x, a00);  a01 = ffma2(h0, f.y, a01);
            a10 = ffma2(h1, f.x, a10);  a11 = ffma2(h1, f.y, a11);
            a20 = ffma2(h2, f.x, a20);  a21 = ffma2(h2, f.y, a21);
            a30 = ffma2(h3, f.x, a30);  a31 = ffma2(h3, f.y, a31);
        }
    }

    // local weighted square sum: sum_e de_inv[e] * sum_d M^2 over this thread's 4e x 4d
    float local = 0.0f;
    {
        unsigned long long accs[4][2] = {{a00, a01}, {a10, a11}, {a20, a21}, {a30, a31}};
        #pragma unroll
        for (int i = 0; i < 4; ++i) {
            float s = 0.0f;
            #pragma unroll
            for (int j = 0; j < 2; ++j) {
                float x, y;
                unpack2(accs[i][j], x, y);
                s += x * x + y * y;
            }
            local += g_deinv[e0 + te * 4 + i] * s;
        }
    }

    // deterministic block tree reduction
    red[t] = local;
    __syncthreads();
    #pragma unroll
    for (int s = 64; s > 0; s >>= 1) {
        if (t < s) red[t] += red[t + s];
        __syncthreads();
    }
    if (t == 0) g_blocksum[tile] = red[0];
}

// ---------------- final: loss = (sum F^2 - S) / N ----------------------------
__global__ void final_kernel(const float* __restrict__ F, float* __restrict__ out,
                             int N, int nblocks) {
    __shared__ float red[256];
    int t = threadIdx.x;
    float sF2 = 0.0f;
    int total = N * 128;
    for (int i = t; i < total; i += 256) {
        float v = F[i];
        sF2 += v * v;
    }
    float bs = 0.0f;
    for (int i = t; i < nblocks; i += 256) bs += g_blocksum[i];
    red[t] = sF2 - bs;
    __syncthreads();
    #pragma unroll
    for (int s = 128; s > 0; s >>= 1) {
        if (t < s) red[t] += red[t + s];
        __syncthreads();
    }
    if (t == 0) out[0] = red[0] / (float)N;
}

// ---------------- launch -----------------------------------------------------
extern "C" void kernel_launch(void* const* d_in, const int* in_sizes, int n_in,
                              void* d_out, int out_size) {
    const float* F  = (const float*)d_in[0];   // [N,128]
    const float* H  = (const float*)d_in[1];   // [N,E]
    const float* Dv = (const float*)d_in[2];   // [N,N]
    const float* De = (const float*)d_in[3];   // [E,E]
    float* out = (float*)d_out;

    int N = in_sizes[0] / 128;                 // 10000
    int E = in_sizes[1] / N;                   // 5000

    int etiles = (E + BE - 1) / BE;            // 157
    int nblocks = etiles * 2;                  // d split into 2 halves of 64

    int prep_threads = N * 128;
    prep_kernel<<<(prep_threads + 255) / 256, 256>>>(F, Dv, De, N, E, 5120);
    gemm_kernel<<<nblocks, 128>>>(H, N, E, etiles);
    final_kernel<<<1, 256>>>(F, out, N, nblocks);
}

// round 3
// speedup vs baseline: 8.0736x; 8.0736x over previous
#include <cuda_runtime.h>
#include <cuda_bf16.h>
#include <stdint.h>
#include <math.h>

#define EPSF 1e-8f
#define DD 128               // d
#define KPAD 10048           // 157*64 padded K (= problem N)
#define NCHUNKS 157
#define EPAD 5120
#define EPITCH 5056          // 79*64
#define NKS 4                // K splits

// ---------------- static device scratch (no allocation) ----------------------
static __device__ __align__(256) __nv_bfloat16 g_FsT[DD * KPAD];     // Fs^T K-major bf16
static __device__ __align__(256) float g_Mpart[NKS * DD * EPITCH];   // 10.35 MB partials
static __device__ float g_dvis[KPAD];
static __device__ float g_deinv[EPAD];
static __device__ float g_blocksum[256];
static __device__ float g_f2sum[256];

// ---------------- helpers ----------------------------------------------------
__device__ __forceinline__ uint32_t smem_u32(const void* p) {
    uint32_t a;
    asm("{ .reg .u64 t; cvta.to.shared.u64 t, %1; cvt.u32.u64 %0, t; }"
        : "=r"(a) : "l"(p));
    return a;
}
#define SWZ(o) ((o) ^ (((o) >> 3) & 0x70))

__device__ __forceinline__ void sts128(uint32_t addr, uint32_t a, uint32_t b,
                                       uint32_t c, uint32_t d) {
    asm volatile("st.shared.v4.b32 [%0], {%1,%2,%3,%4};"
                 :: "r"(addr), "r"(a), "r"(b), "r"(c), "r"(d) : "memory");
}
#define CPA16(dst, src) \
    asm volatile("cp.async.ca.shared.global [%0], [%1], 16;" \
                 :: "r"(dst), "l"(src) : "memory")
#define CPA_COMMIT() asm volatile("cp.async.commit_group;" ::: "memory")
#define CPA_WAIT0()  asm volatile("cp.async.wait_group 0;" ::: "memory")

#define LDSM4(r, addr) \
    asm volatile("ldmatrix.sync.aligned.m8n8.x4.shared.b16 {%0,%1,%2,%3}, [%4];" \
                 : "=r"((r)[0]), "=r"((r)[1]), "=r"((r)[2]), "=r"((r)[3]) : "r"(addr))
#define LDSM4T(r, addr) \
    asm volatile("ldmatrix.sync.aligned.m8n8.x4.trans.shared.b16 {%0,%1,%2,%3}, [%4];" \
                 : "=r"((r)[0]), "=r"((r)[1]), "=r"((r)[2]), "=r"((r)[3]) : "r"(addr))

__device__ __forceinline__ void mma16816(float* c, const uint32_t* a,
                                         uint32_t b0, uint32_t b1) {
    asm volatile(
        "mma.sync.aligned.m16n8k16.row.col.f32.bf16.bf16.f32 "
        "{%0,%1,%2,%3}, {%4,%5,%6,%7}, {%8,%9}, {%0,%1,%2,%3};"
        : "+f"(c[0]), "+f"(c[1]), "+f"(c[2]), "+f"(c[3])
        : "r"(a[0]), "r"(a[1]), "r"(a[2]), "r"(a[3]), "r"(b0), "r"(b1));
}

// ---------------- prep 1: diagonals ------------------------------------------
__global__ void prep_scalars(const float* __restrict__ Dv,
                             const float* __restrict__ De, int Nn, int Ee) {
    int i = blockIdx.x * blockDim.x + threadIdx.x;
    if (i < KPAD) g_dvis[i]  = (i < Nn) ? rsqrtf(Dv[(size_t)i * Nn + i] + EPSF) : 0.f;
    if (i < EPAD) g_deinv[i] = (i < Ee) ? 1.f / (De[(size_t)i * Ee + i] + EPSF) : 0.f;
}

// ---------------- prep 2: FsT (bf16 transpose) + sum(F^2) --------------------
__global__ void __launch_bounds__(256, 4)
prep_fst(const float* __restrict__ F, int Nn) {
    __shared__ __nv_bfloat16 s[64][132];
    __shared__ float red[256];
    const int t = threadIdx.x;
    const int n0 = blockIdx.x * 64;
    float f2 = 0.f;
    #pragma unroll
    for (int i = 0; i < 8; ++i) {
        int g = t + 256 * i;
        int nl = g >> 5;
        int d4 = (g & 31) * 4;
        int n = n0 + nl;
        float4 v = make_float4(0.f, 0.f, 0.f, 0.f);
        float sc = 0.f;
        if (n < Nn) { v = *(const float4*)&F[(size_t)n * DD + d4]; sc = g_dvis[n]; }
        f2 += v.x * v.x + v.y * v.y + v.z * v.z + v.w * v.w;
        s[nl][d4 + 0] = __float2bfloat16(v.x * sc);
        s[nl][d4 + 1] = __float2bfloat16(v.y * sc);
        s[nl][d4 + 2] = __float2bfloat16(v.z * sc);
        s[nl][d4 + 3] = __float2bfloat16(v.w * sc);
    }
    __syncthreads();
    {
        int d = t >> 1;
        int nh = (t & 1) * 32;
        uint32_t w[16];
        #pragma unroll
        for (int j = 0; j < 16; ++j) {
            __nv_bfloat162 p;
            p.x = s[nh + 2 * j][d];
            p.y = s[nh + 2 * j + 1][d];
            w[j] = *(uint32_t*)&p;
        }
        uint4* dst = (uint4*)&g_FsT[(size_t)d * KPAD + n0 + nh];
        dst[0] = make_uint4(w[0],  w[1],  w[2],  w[3]);
        dst[1] = make_uint4(w[4],  w[5],  w[6],  w[7]);
        dst[2] = make_uint4(w[8],  w[9],  w[10], w[11]);
        dst[3] = make_uint4(w[12], w[13], w[14], w[15]);
    }
    red[t] = f2;
    __syncthreads();
    #pragma unroll
    for (int s2 = 128; s2 > 0; s2 >>= 1) {
        if (t < s2) red[t] += red[t + s2];
        __syncthreads();
    }
    if (t == 0) g_f2sum[blockIdx.x] = red[0];
}

// ---------------- GEMM: mma.sync bf16, CTA tile 128(d) x 64(e), K-split ------
// SMEM: A buffers 2x16KB at 0, B buffers 2x8KB at 32768. Total 48KB static.
__global__ void __launch_bounds__(256, 2)
gemm_kernel(const float* __restrict__ H, int Nn, int Ee) {
    __shared__ __align__(1024) char smem[49152];
    const uint32_t sb = smem_u32(smem);
    const uint32_t aB0 = sb, aB1 = sb + 16384;
    const uint32_t bB0 = sb + 32768, bB1 = sb + 40960;

    const int t = threadIdx.x;
    const int lane = t & 31;
    const int wid = t >> 5;
    const int wm = wid & 3;            // 4 m-warps
    const int wn = wid >> 2;           // 2 n-warps
    const int m0 = wm * 32;
    const int n0w = wn * 32;

    const int e0 = blockIdx.x * 64;
    const int ks = blockIdx.y;
    const int c0 = ks * 40;
    const int c1 = min(NCHUNKS, c0 + 40);
    const int nch = c1 - c0;
    const bool tail = (e0 + 64 > Ee);

    const int krow = t >> 2;           // 0..63
    const int ecol = (t & 3) * 16;     // element offset within e-tile

    float acc[2][4][4];
    #pragma unroll
    for (int i = 0; i < 2; ++i)
        #pragma unroll
        for (int j = 0; j < 4; ++j)
            #pragma unroll
            for (int q = 0; q < 4; ++q) acc[i][j][q] = 0.f;

    // ldmatrix per-lane offsets (byte, pre-swizzle)
    const int aRow = (lane & 15);           // + m0 + i*16
    const int aKh  = (lane >> 4) * 8;       // + k0
    const int bKr  = (lane & 15);           // + k0
    const int bNc  = (lane >> 4) * 8;       // + n0w + jb*16

    float4 h4[4];

    // ---- helpers as macros over locals ----
#define LOAD_A(buf, chunk) do {                                              \
        int _cg = (chunk);                                                   \
        _Pragma("unroll")                                                    \
        for (int _i = 0; _i < 4; ++_i) {                                     \
            int pos = t + 256 * _i;                                          \
            int row = pos >> 3;                                              \
            int cc  = pos & 7;                                               \
            const __nv_bfloat16* src = &g_FsT[(size_t)row * KPAD + _cg * 64 + cc * 8]; \
            uint32_t off = (uint32_t)(row * 128 + cc * 16);                  \
            CPA16((buf) + SWZ(off), src);                                    \
        }                                                                    \
    } while (0)

#define LDG_H(chunk) do {                                                    \
        int _n = (chunk) * 64 + krow;                                        \
        bool _v = _n < Nn;                                                   \
        const float* _hr = H + (size_t)_n * Ee;                              \
        if (!tail) {                                                         \
            _Pragma("unroll")                                                \
            for (int _j = 0; _j < 4; ++_j)                                   \
                h4[_j] = _v ? *(const float4*)&_hr[e0 + ecol + 4 * _j]       \
                            : make_float4(0.f, 0.f, 0.f, 0.f);               \
        } else {                                                             \
            _Pragma("unroll")                                                \
            for (int _j = 0; _j < 4; ++_j) {                                 \
                int _e = e0 + ecol + 4 * _j;                                 \
                h4[_j].x = (_v && _e + 0 < Ee) ? _hr[_e + 0] : 0.f;          \
                h4[_j].y = (_v && _e + 1 < Ee) ? _hr[_e + 1] : 0.f;          \
                h4[_j].z = (_v && _e + 2 < Ee) ? _hr[_e + 2] : 0.f;          \
                h4[_j].w = (_v && _e + 3 < Ee) ? _hr[_e + 3] : 0.f;          \
            }                                                                \
        }                                                                    \
    } while (0)

#define STS_H(buf) do {                                                      \
        uint32_t w[8];                                                       \
        _Pragma("unroll")                                                    \
        for (int _j = 0; _j < 4; ++_j) {                                     \
            __nv_bfloat162 p0 = __floats2bfloat162_rn(h4[_j].x, h4[_j].y);   \
            __nv_bfloat162 p1 = __floats2bfloat162_rn(h4[_j].z, h4[_j].w);   \
            w[2 * _j]     = *(uint32_t*)&p0;                                 \
            w[2 * _j + 1] = *(uint32_t*)&p1;                                 \
        }                                                                    \
        uint32_t off = (uint32_t)(krow * 128 + ecol * 2);                    \
        sts128((buf) + SWZ(off),      w[0], w[1], w[2], w[3]);               \
        sts128((buf) + SWZ(off + 16), w[4], w[5], w[6], w[7]);               \
    } while (0)

#define COMPUTE(abuf, bbuf) do {                                             \
        _Pragma("unroll")                                                    \
        for (int k0 = 0; k0 < 64; k0 += 16) {                                \
            uint32_t afr[2][4];                                              \
            _Pragma("unroll")                                                \
            for (int i = 0; i < 2; ++i) {                                    \
                uint32_t off = (uint32_t)((m0 + i * 16 + aRow) * 128         \
                                          + (k0 + aKh) * 2);                 \
                LDSM4(afr[i], (abuf) + SWZ(off));                            \
            }                                                                \
            uint32_t bfr[2][4];                                              \
            _Pragma("unroll")                                                \
            for (int jb = 0; jb < 2; ++jb) {                                 \
                uint32_t off = (uint32_t)((k0 + bKr) * 128                   \
                                          + (n0w + jb * 16 + bNc) * 2);      \
                LDSM4T(bfr[jb], (bbuf) + SWZ(off));                          \
            }                                                                \
            _Pragma("unroll")                                                \
            for (int i = 0; i < 2; ++i)                                      \
                _Pragma("unroll")                                            \
                for (int j = 0; j < 4; ++j)                                  \
                    mma16816(acc[i][j], afr[i],                              \
                             bfr[j >> 1][(j & 1) * 2],                       \
                             bfr[j >> 1][(j & 1) * 2 + 1]);                  \
        }                                                                    \
    } while (0)

    // ---- pipeline ----
    LOAD_A(aB0, c0);
    CPA_COMMIT();
    LDG_H(c0);
    CPA_WAIT0();
    STS_H(bB0);
    __syncthreads();

    for (int cc = 0; cc < nch; ++cc) {
        const int b = cc & 1;
        const uint32_t aCur = b ? aB1 : aB0;
        const uint32_t bCur = b ? bB1 : bB0;
        const uint32_t aNxt = b ? aB0 : aB1;
        const uint32_t bNxt = b ? bB0 : bB1;
        const bool has = (cc + 1) < nch;
        if (has) {
            LOAD_A(aNxt, c0 + cc + 1);
            CPA_COMMIT();
            LDG_H(c0 + cc + 1);
        }
        COMPUTE(aCur, bCur);
        if (has) {
            CPA_WAIT0();
            STS_H(bNxt);
        }
        __syncthreads();
    }

    // ---- write partials: g_Mpart[ks][d][e], coalesced float2 ----
    #pragma unroll
    for (int i = 0; i < 2; ++i) {
        #pragma unroll
        for (int j = 0; j < 4; ++j) {
            int d = m0 + i * 16 + (lane >> 2);
            int e = e0 + n0w + j * 8 + (lane & 3) * 2;
            size_t base = ((size_t)(ks * DD + d)) * EPITCH + e;
            float2 v0 = make_float2(acc[i][j][0], acc[i][j][1]);
            float2 v1 = make_float2(acc[i][j][2], acc[i][j][3]);
            *(float2*)&g_Mpart[base] = v0;
            *(float2*)&g_Mpart[base + (size_t)8 * EPITCH] = v1;
        }
    }
}

// ---------------- pass 3: S partials = sum_e deinv * ||sum_ks M||^2 ----------
__global__ void __launch_bounds__(256, 4)
pass3_kernel(int Ee) {
    __shared__ float r[256];
    const int t = threadIdx.x;
    const int e = blockIdx.x * 64 + (t & 63);
    const int dg = t >> 6;
    float acc = 0.f;
    #pragma unroll 4
    for (int d = dg * 32; d < dg * 32 + 32; ++d) {
        float v = 0.f;
        #pragma unroll
        for (int ksi = 0; ksi < NKS; ++ksi)
            v += g_Mpart[((size_t)(ksi * DD + d)) * EPITCH + e];
        acc += v * v;
    }
    r[t] = acc;
    __syncthreads();
    if (t < 64) r[t] = (r[t] + r[t + 64] + r[t + 128] + r[t + 192]) * g_deinv[e];
    __syncthreads();
    #pragma unroll
    for (int s = 32; s > 0; s >>= 1) {
        if (t < s) r[t] += r[t + s];
        __syncthreads();
    }
    if (t == 0) g_blocksum[blockIdx.x] = r[0];
}

// ---------------- final combine ----------------------------------------------
__global__ void final_kernel(float* __restrict__ out, int Nn, int etiles, int nchunks) {
    __shared__ float red[256];
    int t = threadIdx.x;
    float acc = 0.f;
    for (int i = t; i < nchunks; i += 256) acc += g_f2sum[i];
    for (int i = t; i < etiles; i += 256) acc -= g_blocksum[i];
    red[t] = acc;
    __syncthreads();
    #pragma unroll
    for (int s = 128; s > 0; s >>= 1) {
        if (t < s) red[t] += red[t + s];
        __syncthreads();
    }
    if (t == 0) out[0] = red[0] / (float)Nn;
}

// ---------------- launch ------------------------------------------------------
extern "C" void kernel_launch(void* const* d_in, const int* in_sizes, int n_in,
                              void* d_out, int out_size) {
    const float* F  = (const float*)d_in[0];   // [N,128]
    const float* H  = (const float*)d_in[1];   // [N,E]
    const float* Dv = (const float*)d_in[2];   // [N,N]
    const float* De = (const float*)d_in[3];   // [E,E]
    float* out = (float*)d_out;

    int Nn = in_sizes[0] / DD;                 // 10000
    int Ee = in_sizes[1] / Nn;                 // 5000
    int etiles = (Ee + 63) / 64;               // 79

    prep_scalars<<<(KPAD + 255) / 256, 256>>>(Dv, De, Nn, Ee);
    prep_fst<<<NCHUNKS, 256>>>(F, Nn);
    gemm_kernel<<<dim3(etiles, NKS), 256>>>(H, Nn, Ee);
    pass3_kernel<<<etiles, 256>>>(Ee);
    final_kernel<<<1, 256>>>(out, Nn, etiles, NCHUNKS);
}

// round 4
// speedup vs baseline: 8.3794x; 1.0379x over previous
#include <cuda_runtime.h>
#include <cuda_bf16.h>
#include <stdint.h>
#include <math.h>

#define EPSF 1e-8f
#define DD 128               // d
#define KPAD 10048           // 628*16 padded K (= problem N)
#define NCHUNKS 157          // 64-k chunks
#define EPAD 5120
#define EPITCH 5120          // 40*128
#define NKS 7                // K splits
#define CPK 23               // chunks per split (last = 19)

// ---------------- static device scratch (no allocation) ----------------------
static __device__ __align__(256) __nv_bfloat16 g_FsT[DD * KPAD];     // Fs^T K-major bf16
static __device__ __align__(256) float g_Mpart[NKS * DD * EPITCH];   // 18.35 MB partials
static __device__ float g_dvis[KPAD];
static __device__ float g_deinv[EPAD];
static __device__ float g_blocksum[512];
static __device__ float g_f2sum[640];

// ---------------- helpers ----------------------------------------------------
__device__ __forceinline__ uint32_t smem_u32(const void* p) {
    uint32_t a;
    asm("{ .reg .u64 t; cvta.to.shared.u64 t, %1; cvt.u32.u64 %0, t; }"
        : "=r"(a) : "l"(p));
    return a;
}
#define SWZ(o) ((o) ^ (((o) >> 3) & 0x70))

__device__ __forceinline__ void sts128(uint32_t addr, uint32_t a, uint32_t b,
                                       uint32_t c, uint32_t d) {
    asm volatile("st.shared.v4.b32 [%0], {%1,%2,%3,%4};"
                 :: "r"(addr), "r"(a), "r"(b), "r"(c), "r"(d) : "memory");
}
#define CPA16(dst, src) \
    asm volatile("cp.async.ca.shared.global [%0], [%1], 16;" \
                 :: "r"(dst), "l"(src) : "memory")
#define CPA_COMMIT() asm volatile("cp.async.commit_group;" ::: "memory")
#define CPA_WAIT0()  asm volatile("cp.async.wait_group 0;" ::: "memory")

#define LDSM4(r, addr) \
    asm volatile("ldmatrix.sync.aligned.m8n8.x4.shared.b16 {%0,%1,%2,%3}, [%4];" \
                 : "=r"((r)[0]), "=r"((r)[1]), "=r"((r)[2]), "=r"((r)[3]) : "r"(addr))
#define LDSM4T(r, addr) \
    asm volatile("ldmatrix.sync.aligned.m8n8.x4.trans.shared.b16 {%0,%1,%2,%3}, [%4];" \
                 : "=r"((r)[0]), "=r"((r)[1]), "=r"((r)[2]), "=r"((r)[3]) : "r"(addr))

__device__ __forceinline__ void mma16816(float* c, const uint32_t* a,
                                         uint32_t b0, uint32_t b1) {
    asm volatile(
        "mma.sync.aligned.m16n8k16.row.col.f32.bf16.bf16.f32 "
        "{%0,%1,%2,%3}, {%4,%5,%6,%7}, {%8,%9}, {%0,%1,%2,%3};"
        : "+f"(c[0]), "+f"(c[1]), "+f"(c[2]), "+f"(c[3])
        : "r"(a[0]), "r"(a[1]), "r"(a[2]), "r"(a[3]), "r"(b0), "r"(b1));
}

// ---------------- prep 1: diagonals ------------------------------------------
__global__ void prep_scalars(const float* __restrict__ Dv,
                             const float* __restrict__ De, int Nn, int Ee) {
    int i = blockIdx.x * blockDim.x + threadIdx.x;
    if (i < KPAD) g_dvis[i]  = (i < Nn) ? rsqrtf(Dv[(size_t)i * Nn + i] + EPSF) : 0.f;
    if (i < EPAD) g_deinv[i] = (i < Ee) ? 1.f / (De[(size_t)i * Ee + i] + EPSF) : 0.f;
}

// ---------------- prep 2: FsT (bf16 transpose) + sum(F^2), 16 rows/block -----
__global__ void __launch_bounds__(256, 4)
prep_fst(const float* __restrict__ F, int Nn) {
    __shared__ __nv_bfloat16 s[16][132];
    __shared__ float red[256];
    const int t = threadIdx.x;
    const int n0 = blockIdx.x * 16;
    float f2 = 0.f;
    #pragma unroll
    for (int i = 0; i < 2; ++i) {
        int g = t + 256 * i;          // 512 float4 slots (16 n x 32)
        int nl = g >> 5;
        int d4 = (g & 31) * 4;
        int n = n0 + nl;
        float4 v = make_float4(0.f, 0.f, 0.f, 0.f);
        float sc = 0.f;
        if (n < Nn) { v = *(const float4*)&F[(size_t)n * DD + d4]; sc = g_dvis[n]; }
        f2 += v.x * v.x + v.y * v.y + v.z * v.z + v.w * v.w;
        s[nl][d4 + 0] = __float2bfloat16(v.x * sc);
        s[nl][d4 + 1] = __float2bfloat16(v.y * sc);
        s[nl][d4 + 2] = __float2bfloat16(v.z * sc);
        s[nl][d4 + 3] = __float2bfloat16(v.w * sc);
    }
    __syncthreads();
    {   // transposed write: thread -> (d, 8 n values) = one uint4
        int d = t >> 1;
        int nh = (t & 1) * 8;
        uint32_t w[4];
        #pragma unroll
        for (int j = 0; j < 4; ++j) {
            __nv_bfloat162 p;
            p.x = s[nh + 2 * j][d];
            p.y = s[nh + 2 * j + 1][d];
            w[j] = *(uint32_t*)&p;
        }
        *(uint4*)&g_FsT[(size_t)d * KPAD + n0 + nh] = make_uint4(w[0], w[1], w[2], w[3]);
    }
    red[t] = f2;
    __syncthreads();
    #pragma unroll
    for (int s2 = 128; s2 > 0; s2 >>= 1) {
        if (t < s2) red[t] += red[t + s2];
        __syncthreads();
    }
    if (t == 0) g_f2sum[blockIdx.x] = red[0];
}

// ---------------- GEMM: mma.sync bf16, CTA tile 128(d) x 128(e), K-split -----
// Dynamic SMEM 64KB: A 2x16KB @0, B 2x16KB @32768 (each = Blo 8KB + Bhi 8KB)
__global__ void __launch_bounds__(256, 2)
gemm_kernel(const float* __restrict__ H, int Nn, int Ee) {
    extern __shared__ __align__(1024) char smem[];
    const uint32_t sb = smem_u32(smem);

    const int t = threadIdx.x;
    const int lane = t & 31;
    const int wid = t >> 5;
    const int wm = wid & 3;            // 4 m-warps
    const int wn = wid >> 2;           // 2 n-warps (64 e each)
    const int m0 = wm * 32;

    const int e0 = blockIdx.x * 128;
    const int ks = blockIdx.y;
    const int c0 = ks * CPK;
    const int c1 = min(NCHUNKS, c0 + CPK);
    const int nch = c1 - c0;
    const bool tail = (e0 + 128 > Ee);

    const int krow = t >> 2;           // 0..63
    const int ecol = (t & 3) * 32;     // 32 e per thread
    // per-thread fixed B region select (e-half) and in-half e offset
    const int eloc = ecol & 63;

    float acc[2][8][4];
    #pragma unroll
    for (int i = 0; i < 2; ++i)
        #pragma unroll
        for (int j = 0; j < 8; ++j)
            #pragma unroll
            for (int q = 0; q < 4; ++q) acc[i][j][q] = 0.f;

    // ldmatrix per-lane offsets
    const int aRow = (lane & 15);
    const int aKh  = (lane >> 4) * 8;
    const int bKr  = (lane & 15);
    const int bNc  = (lane >> 4) * 8;

    uint32_t w[16];                    // converted B staging (bf16x2)

#define LOAD_A(buf, chunk) do {                                              \
        int _cg = (chunk);                                                   \
        _Pragma("unroll")                                                    \
        for (int _i = 0; _i < 4; ++_i) {                                     \
            int pos = t + 256 * _i;                                          \
            int row = pos >> 3;                                              \
            int cc  = pos & 7;                                               \
            const __nv_bfloat16* src = &g_FsT[(size_t)row * KPAD + _cg * 64 + cc * 8]; \
            uint32_t off = (uint32_t)(row * 128 + cc * 16);                  \
            CPA16((buf) + SWZ(off), src);                                    \
        }                                                                    \
    } while (0)

#define LDG_H(chunk) do {                                                    \
        int _n = (chunk) * 64 + krow;                                        \
        bool _v = _n < Nn;                                                   \
        const float* _hr = H + (size_t)_n * Ee;                              \
        _Pragma("unroll")                                                    \
        for (int _j = 0; _j < 8; ++_j) {                                     \
            float4 f;                                                        \
            if (!tail) {                                                     \
                f = _v ? *(const float4*)&_hr[e0 + ecol + 4 * _j]            \
                       : make_float4(0.f, 0.f, 0.f, 0.f);                    \
            } else {                                                         \
                int _e = e0 + ecol + 4 * _j;                                 \
                f.x = (_v && _e + 0 < Ee) ? _hr[_e + 0] : 0.f;               \
                f.y = (_v && _e + 1 < Ee) ? _hr[_e + 1] : 0.f;               \
                f.z = (_v && _e + 2 < Ee) ? _hr[_e + 2] : 0.f;               \
                f.w = (_v && _e + 3 < Ee) ? _hr[_e + 3] : 0.f;               \
            }                                                                \
            __nv_bfloat162 p0 = __floats2bfloat162_rn(f.x, f.y);             \
            __nv_bfloat162 p1 = __floats2bfloat162_rn(f.z, f.w);             \
            w[2 * _j]     = *(uint32_t*)&p0;                                 \
            w[2 * _j + 1] = *(uint32_t*)&p1;                                 \
        }                                                                    \
    } while (0)

#define STS_H(bbase) do {                                                    \
        uint32_t reg = (bbase) + ((t & 2) ? 8192u : 0u);                     \
        uint32_t off = (uint32_t)(krow * 128 + eloc * 2);                    \
        sts128(reg + SWZ(off),      w[0],  w[1],  w[2],  w[3]);              \
        sts128(reg + SWZ(off + 16), w[4],  w[5],  w[6],  w[7]);              \
        sts128(reg + SWZ(off + 32), w[8],  w[9],  w[10], w[11]);             \
        sts128(reg + SWZ(off + 48), w[12], w[13], w[14], w[15]);             \
    } while (0)

#define COMPUTE(abuf, bbase) do {                                            \
        uint32_t breg = (bbase) + (wn ? 8192u : 0u);                         \
        _Pragma("unroll")                                                    \
        for (int k0 = 0; k0 < 64; k0 += 16) {                                \
            uint32_t afr[2][4];                                              \
            _Pragma("unroll")                                                \
            for (int i = 0; i < 2; ++i) {                                    \
                uint32_t off = (uint32_t)((m0 + i * 16 + aRow) * 128         \
                                          + (k0 + aKh) * 2);                 \
                LDSM4(afr[i], (abuf) + SWZ(off));                            \
            }                                                                \
            uint32_t bfr[4][4];                                              \
            _Pragma("unroll")                                                \
            for (int jb = 0; jb < 4; ++jb) {                                 \
                uint32_t off = (uint32_t)((k0 + bKr) * 128                   \
                                          + (jb * 16 + bNc) * 2);            \
                LDSM4T(bfr[jb], breg + SWZ(off));                            \
            }                                                                \
            _Pragma("unroll")                                                \
            for (int i = 0; i < 2; ++i)                                      \
                _Pragma("unroll")                                            \
                for (int j = 0; j < 8; ++j)                                  \
                    mma16816(acc[i][j], afr[i],                              \
                             bfr[j >> 1][(j & 1) * 2],                       \
                             bfr[j >> 1][(j & 1) * 2 + 1]);                  \
        }                                                                    \
    } while (0)

    // ---- pipeline (double-buffered) ----
    LOAD_A(sb, c0);
    CPA_COMMIT();
    LDG_H(c0);
    CPA_WAIT0();
    STS_H(sb + 32768);
    __syncthreads();

    for (int cc = 0; cc < nch; ++cc) {
        const int b = cc & 1;
        const uint32_t aCur = sb + b * 16384;
        const uint32_t bCur = sb + 32768 + b * 16384;
        const uint32_t aNxt = sb + (b ^ 1) * 16384;
        const uint32_t bNxt = sb + 32768 + (b ^ 1) * 16384;
        const bool has = (cc + 1) < nch;
        if (has) {
            LOAD_A(aNxt, c0 + cc + 1);
            CPA_COMMIT();
            LDG_H(c0 + cc + 1);
        }
        COMPUTE(aCur, bCur);
        if (has) {
            CPA_WAIT0();
            STS_H(bNxt);
        }
        __syncthreads();
    }

    // ---- write partials: g_Mpart[ks][d][e] ----
    #pragma unroll
    for (int i = 0; i < 2; ++i) {
        #pragma unroll
        for (int j = 0; j < 8; ++j) {
            int d = m0 + i * 16 + (lane >> 2);
            int e = e0 + wn * 64 + j * 8 + (lane & 3) * 2;
            size_t base = ((size_t)(ks * DD + d)) * EPITCH + e;
            *(float2*)&g_Mpart[base] = make_float2(acc[i][j][0], acc[i][j][1]);
            *(float2*)&g_Mpart[base + (size_t)8 * EPITCH] =
                make_float2(acc[i][j][2], acc[i][j][3]);
        }
    }
}

// ---------------- pass 3: S partials = sum_e deinv * ||sum_ks M||^2 ----------
__global__ void __launch_bounds__(256, 4)
pass3_kernel() {
    __shared__ float r[256];
    const int t = threadIdx.x;
    const int e = blockIdx.x * 128 + (t & 127);
    const int d0 = blockIdx.y * 16 + (t >> 7) * 8;
    float acc = 0.f;
    #pragma unroll
    for (int dd = 0; dd < 8; ++dd) {
        int d = d0 + dd;
        float v = 0.f;
        #pragma unroll
        for (int ksi = 0; ksi < NKS; ++ksi)
            v += g_Mpart[((size_t)(ksi * DD + d)) * EPITCH + e];
        acc += v * v;
    }
    acc *= g_deinv[e];
    r[t] = acc;
    __syncthreads();
    #pragma unroll
    for (int s = 128; s > 0; s >>= 1) {
        if (t < s) r[t] += r[t + s];
        __syncthreads();
    }
    if (t == 0) g_blocksum[blockIdx.x * 8 + blockIdx.y] = r[0];
}

// ---------------- final combine ----------------------------------------------
__global__ void final_kernel(float* __restrict__ out, int Nn, int nsum, int nprep) {
    __shared__ float red[256];
    int t = threadIdx.x;
    float acc = 0.f;
    for (int i = t; i < nprep; i += 256) acc += g_f2sum[i];
    for (int i = t; i < nsum; i += 256) acc -= g_blocksum[i];
    red[t] = acc;
    __syncthreads();
    #pragma unroll
    for (int s = 128; s > 0; s >>= 1) {
        if (t < s) red[t] += red[t + s];
        __syncthreads();
    }
    if (t == 0) out[0] = red[0] / (float)Nn;
}

// ---------------- launch ------------------------------------------------------
extern "C" void kernel_launch(void* const* d_in, const int* in_sizes, int n_in,
                              void* d_out, int out_size) {
    const float* F  = (const float*)d_in[0];   // [N,128]
    const float* H  = (const float*)d_in[1];   // [N,E]
    const float* Dv = (const float*)d_in[2];   // [N,N]
    const float* De = (const float*)d_in[3];   // [E,E]
    float* out = (float*)d_out;

    int Nn = in_sizes[0] / DD;                 // 10000
    int Ee = in_sizes[1] / Nn;                 // 5000
    int etiles = (Ee + 127) / 128;             // 40
    int nprep = KPAD / 16;                     // 628

    cudaFuncSetAttribute(gemm_kernel, cudaFuncAttributeMaxDynamicSharedMemorySize,
                         65536);

    prep_scalars<<<(KPAD + 255) / 256, 256>>>(Dv, De, Nn, Ee);
    prep_fst<<<nprep, 256>>>(F, Nn);
    gemm_kernel<<<dim3(etiles, NKS), 256, 65536>>>(H, Nn, Ee);
    pass3_kernel<<<dim3(etiles, 8), 256>>>();
    final_kernel<<<1, 256>>>(out, Nn, etiles * 8, nprep);
}